// round 9
// baseline (speedup 1.0000x reference)
#include <cuda_runtime.h>
#include <cstdint>
#include <cstddef>

// ============================================================================
// Problem constants
// ============================================================================
#define E_ROWS   500000
#define OUT_N    256
#define K1       384        // 2*128 + 64 + 64
#define K2       256
#define D_NODE   128
#define D_EDGE   64
#define D_U      64
#define BN_EPS   1e-5

#define TILE_M   128
#define BK       32
#define N_TILES  ((E_ROWS + TILE_M - 1) / TILE_M)   // 3907
#define THREADS  512

// SMEM padded strides (floats) — proven conflict-free for fragment LDS
#define ASTR 36      // A: 128 rows x 32 cols, stride 36
#define BSTR 264     // B: 32 rows x 256 cols, stride 264

// SMEM layout (bytes)
#define SM_AFF   0                       // 512 floats (scale|shift) for layer 1
#define SM_A0    2048
#define SM_A1    (SM_A0 + 128*ASTR*4)    // 20480
#define SM_B0    (SM_A1 + 128*ASTR*4)    // 38912
#define SM_B1    (SM_B0 + BK*BSTR*4)     // 72704
#define SMEM_TOTAL (SM_B1 + BK*BSTR*4)   // 106496

// ============================================================================
// Scratch (static __device__ — no allocations allowed)
// ============================================================================
__device__ __align__(16) float g_y1[(size_t)E_ROWS * OUT_N];   // 512 MB
__device__ __align__(16) float g_y2[(size_t)E_ROWS * OUT_N];   // 512 MB
__device__ __align__(16) float g_W1r[K1 * OUT_N];              // tf32-rounded W1 [384][256]
__device__ __align__(16) float g_W2r[K2 * OUT_N];              // tf32-rounded W2 [256][256]
__device__ __align__(16) float g_part_sum[4096 * OUT_N];
__device__ __align__(16) float g_part_sq [4096 * OUT_N];
__device__ __align__(16) float g_scale1[OUT_N], g_shift1[OUT_N];
__device__ __align__(16) float g_scale2[OUT_N], g_shift2[OUT_N];

// ============================================================================
// Helpers
// ============================================================================
__device__ __forceinline__ float to_tf32(float x) {
    uint32_t r;
    asm("cvt.rna.tf32.f32 %0, %1;" : "=r"(r) : "f"(x));
    return __uint_as_float(r);
}
__device__ __forceinline__ uint32_t to_tf32_u(float x) {
    uint32_t r;
    asm("cvt.rna.tf32.f32 %0, %1;" : "=r"(r) : "f"(x));
    return r;
}
__device__ __forceinline__ uint32_t smem_to_u32(const void* p) {
    uint32_t a;
    asm("{ .reg .u64 t; cvta.to.shared.u64 t, %1; cvt.u32.u64 %0, t; }" : "=r"(a) : "l"(p));
    return a;
}
__device__ __forceinline__ void cp16(uint32_t dst_smem, const void* src) {
    asm volatile("cp.async.cg.shared.global [%0], [%1], 16;"
                 :: "r"(dst_smem), "l"(src) : "memory");
}
__device__ __forceinline__ void cp_commit() {
    asm volatile("cp.async.commit_group;" ::: "memory");
}

// m16n8k8 tf32 MMA: D += A(16x8, row) * B(8x8, col)
__device__ __forceinline__ void mma8(float* c, const uint32_t* a, uint32_t b0, uint32_t b1) {
    asm volatile(
        "mma.sync.aligned.m16n8k8.row.col.f32.tf32.tf32.f32 "
        "{%0,%1,%2,%3}, {%4,%5,%6,%7}, {%8,%9}, {%0,%1,%2,%3};"
        : "+f"(c[0]), "+f"(c[1]), "+f"(c[2]), "+f"(c[3])
        : "r"(a[0]), "r"(a[1]), "r"(a[2]), "r"(a[3]), "r"(b0), "r"(b1));
}

// ============================================================================
// Kernel 1: tf32-round weights (keep original [K][N] layout)
// ============================================================================
__global__ void k_prep(const float* __restrict__ W1, const float* __restrict__ W2) {
    int i = blockIdx.x * blockDim.x + threadIdx.x;
    if (i < K1 * OUT_N)            g_W1r[i] = to_tf32(W1[i]);
    else if (i - K1 * OUT_N < K2 * OUT_N) {
        int j = i - K1 * OUT_N;
        g_W2r[j] = to_tf32(W2[j]);
    }
}

// ============================================================================
// Tile loaders (cp.async into padded SMEM)
// NOTE: batch is int32 — JAX default config downcasts jnp.int64 randint to
// int32, and the harness only materializes f32/i32/bf16. Reading it as int64
// was the source of the R8 illegal-memory-access.
// ============================================================================
template <int LAYER>
__device__ __forceinline__ void load_tiles(
    char* smem, uint32_t sbase, int buf, int kc, int tid, int m0,
    const float* __restrict__ src, const float* __restrict__ dst,
    const float* __restrict__ edge, const float* __restrict__ u,
    const int* __restrict__ batch)
{
    const int k0 = kc * BK;
    const uint32_t aoff = sbase + (buf ? SM_A1 : SM_A0);
    const uint32_t boff = sbase + (buf ? SM_B1 : SM_B0);

    // ---- A tile: 128 rows x 32 cols = 1024 x 16B chunks, 2 per thread ----
    #pragma unroll
    for (int i = 0; i < 2; i++) {
        int id = tid + i * THREADS;
        int r = id >> 3;
        int c4 = (id & 7) * 4;
        long long grow = m0 + r;
        if (grow >= E_ROWS) grow = E_ROWS - 1;
        const float* sp;
        if (LAYER == 0) {
            if (k0 < 128)       sp = src  + grow * D_NODE + (k0      ) + c4;
            else if (k0 < 256)  sp = dst  + grow * D_NODE + (k0 - 128) + c4;
            else if (k0 < 320)  sp = edge + grow * D_EDGE + (k0 - 256) + c4;
            else {
                long long b = (long long)batch[grow];
                sp = u + b * D_U + (k0 - 320) + c4;
            }
        } else {
            sp = g_y1 + grow * (long long)OUT_N + k0 + c4;
        }
        cp16(aoff + (uint32_t)(r * ASTR + c4) * 4u, sp);
    }

    // ---- B tile: 32 rows x 256 cols = 2048 x 16B chunks, 4 per thread ----
    const float* __restrict__ W = (LAYER == 0) ? g_W1r : g_W2r;
    #pragma unroll
    for (int i = 0; i < 4; i++) {
        int id = tid + i * THREADS;
        int r = id >> 6;
        int c = (id & 63) * 4;
        cp16(boff + (uint32_t)(r * BSTR + c) * 4u, W + (size_t)(k0 + r) * OUT_N + c);
    }
    cp_commit();
}

// ============================================================================
// Kernel 2/4: GEMM (128x256 CTA tile, 32x64 warp tile, m16n8k8 tf32)
//   LAYER 0: A = concat(src,dest,edge,u[batch]) -> g_y1 + stats partials
//   LAYER 1: A = relu(bn1(g_y1)) (fused at fragment load) -> g_y2 + partials
// ============================================================================
template <int LAYER>
__global__ __launch_bounds__(THREADS, 1) void k_gemm(
    const float* __restrict__ src, const float* __restrict__ dst,
    const float* __restrict__ edge, const float* __restrict__ u,
    const int* __restrict__ batch)
{
    extern __shared__ char smem[];
    const uint32_t sbase = smem_to_u32(smem);
    const int tid   = threadIdx.x;
    const int wid   = tid >> 5;
    const int lane  = tid & 31;
    const int g     = lane >> 2;       // 0..7
    const int t     = lane & 3;        // 0..3
    const int warp_m = wid & 3;        // 4 row-warps of 32 rows
    const int warp_n = wid >> 2;       // 4 col-warps of 64 cols
    const int m0 = blockIdx.x * TILE_M;
    const int NK = (LAYER == 0) ? (K1 / BK) : (K2 / BK);

    float* aff = (float*)(smem + SM_AFF);
    if (LAYER == 1) {
        if (tid < 256)      aff[tid]       = g_scale1[tid];
        else                aff[tid]       = g_shift1[tid - 256];  // aff[256..511]
        __syncthreads();
    }

    float acc[2][8][4];
    #pragma unroll
    for (int mt = 0; mt < 2; mt++)
        #pragma unroll
        for (int nt = 0; nt < 8; nt++)
            #pragma unroll
            for (int j = 0; j < 4; j++) acc[mt][nt][j] = 0.f;

    load_tiles<LAYER>(smem, sbase, 0, 0, tid, m0, src, dst, edge, u, batch);

    for (int kc = 0; kc < NK; kc++) {
        const int buf = kc & 1;
        if (kc + 1 < NK) {
            load_tiles<LAYER>(smem, sbase, buf ^ 1, kc + 1, tid, m0, src, dst, edge, u, batch);
            asm volatile("cp.async.wait_group 1;" ::: "memory");
        } else {
            asm volatile("cp.async.wait_group 0;" ::: "memory");
        }
        __syncthreads();

        const float* As = (const float*)(smem + (buf ? SM_A1 : SM_A0));
        const float* Bs = (const float*)(smem + (buf ? SM_B1 : SM_B0));
        const float* Ap = As + (warp_m * 32 + g) * ASTR + t;
        const float* Bp = Bs + t * BSTR + warp_n * 64 + g;

        #pragma unroll
        for (int ks = 0; ks < 4; ks++) {
            // A fragments: a0(g,t) a1(g+8,t) a2(g,t+4) a3(g+8,t+4)
            float af[2][4];
            #pragma unroll
            for (int mt = 0; mt < 2; mt++) {
                af[mt][0] = Ap[(mt * 16    ) * ASTR + ks * 8    ];
                af[mt][1] = Ap[(mt * 16 + 8) * ASTR + ks * 8    ];
                af[mt][2] = Ap[(mt * 16    ) * ASTR + ks * 8 + 4];
                af[mt][3] = Ap[(mt * 16 + 8) * ASTR + ks * 8 + 4];
            }
            if (LAYER == 1) {
                const int kk = kc * 32 + ks * 8;
                float s0 = aff[kk + t],       h0 = aff[256 + kk + t];
                float s4 = aff[kk + t + 4],   h4 = aff[256 + kk + t + 4];
                #pragma unroll
                for (int mt = 0; mt < 2; mt++) {
                    af[mt][0] = fmaxf(fmaf(af[mt][0], s0, h0), 0.f);
                    af[mt][1] = fmaxf(fmaf(af[mt][1], s0, h0), 0.f);
                    af[mt][2] = fmaxf(fmaf(af[mt][2], s4, h4), 0.f);
                    af[mt][3] = fmaxf(fmaf(af[mt][3], s4, h4), 0.f);
                }
            }
            uint32_t ua[2][4];
            #pragma unroll
            for (int mt = 0; mt < 2; mt++)
                #pragma unroll
                for (int j = 0; j < 4; j++) ua[mt][j] = to_tf32_u(af[mt][j]);

            // B fragments: b0(k=t, n=g), b1(k=t+4, n=g) — pre-rounded in k_prep
            uint32_t b0[8], b1[8];
            #pragma unroll
            for (int nt = 0; nt < 8; nt++) {
                b0[nt] = __float_as_uint(Bp[(ks * 8    ) * BSTR + nt * 8]);
                b1[nt] = __float_as_uint(Bp[(ks * 8 + 4) * BSTR + nt * 8]);
            }
            #pragma unroll
            for (int mt = 0; mt < 2; mt++)
                #pragma unroll
                for (int nt = 0; nt < 8; nt++)
                    mma8(acc[mt][nt], ua[mt], b0[nt], b1[nt]);
        }
        __syncthreads();
    }

    // ================= Epilogue: store y + column sum/sumsq partials ========
    float* __restrict__ ybuf = (LAYER == 0) ? g_y1 : g_y2;
    float* sm_ps = (float*)(smem + SM_A0);          // [4][256]
    float* sm_sq = sm_ps + 4 * OUT_N;               // [4][256]

    const int r_base = m0 + warp_m * 32 + g;

    #pragma unroll
    for (int nt = 0; nt < 8; nt++) {
        const int col = warp_n * 64 + nt * 8 + 2 * t;
        float v0 = 0.f, v1 = 0.f, q0 = 0.f, q1 = 0.f;
        #pragma unroll
        for (int mt = 0; mt < 2; mt++) {
            const long long r1 = r_base + mt * 16;
            const long long r2 = r1 + 8;
            float c0 = acc[mt][nt][0], c1 = acc[mt][nt][1];
            float c2 = acc[mt][nt][2], c3 = acc[mt][nt][3];
            if (r1 < E_ROWS) {
                *(float2*)(ybuf + r1 * OUT_N + col) = make_float2(c0, c1);
                v0 += c0; v1 += c1; q0 += c0 * c0; q1 += c1 * c1;
            }
            if (r2 < E_ROWS) {
                *(float2*)(ybuf + r2 * OUT_N + col) = make_float2(c2, c3);
                v0 += c2; v1 += c3; q0 += c2 * c2; q1 += c3 * c3;
            }
        }
        // reduce over the 8 lanes sharing t (g spans lane bits 2..4)
        #pragma unroll
        for (int o = 4; o < 32; o <<= 1) {
            v0 += __shfl_xor_sync(0xffffffffu, v0, o);
            v1 += __shfl_xor_sync(0xffffffffu, v1, o);
            q0 += __shfl_xor_sync(0xffffffffu, q0, o);
            q1 += __shfl_xor_sync(0xffffffffu, q1, o);
        }
        if (g == 0) {
            sm_ps[warp_m * OUT_N + col]     = v0;
            sm_ps[warp_m * OUT_N + col + 1] = v1;
            sm_sq[warp_m * OUT_N + col]     = q0;
            sm_sq[warp_m * OUT_N + col + 1] = q1;
        }
    }
    __syncthreads();

    if (tid < OUT_N) {
        float s = 0.f, q = 0.f;
        #pragma unroll
        for (int wm = 0; wm < 4; wm++) {
            s += sm_ps[wm * OUT_N + tid];
            q += sm_sq[wm * OUT_N + tid];
        }
        g_part_sum[(size_t)blockIdx.x * OUT_N + tid] = s;
        g_part_sq [(size_t)blockIdx.x * OUT_N + tid] = q;
    }
}

// ============================================================================
// Kernel 3/5: finalize BN stats (deterministic fixed-order, double accum)
// ============================================================================
__global__ void k_reduce(const float* __restrict__ g, const float* __restrict__ b, int layer) {
    int c = threadIdx.x;  // 256 threads
    double s = 0.0, q = 0.0;
    for (int tt = 0; tt < N_TILES; tt++) {
        s += (double)g_part_sum[(size_t)tt * OUT_N + c];
        q += (double)g_part_sq [(size_t)tt * OUT_N + c];
    }
    double m   = s / (double)E_ROWS;
    double var = q / (double)E_ROWS - m * m;
    float rstd = (float)(1.0 / sqrt(var + BN_EPS));
    float scale = g[c] * rstd;
    float shift = b[c] - (float)m * scale;
    if (layer == 0) { g_scale1[c] = scale; g_shift1[c] = shift; }
    else            { g_scale2[c] = scale; g_shift2[c] = shift; }
}

// ============================================================================
// Kernel 6: out = y2 * scale2 + shift2
// ============================================================================
__global__ void k_finalize(float* __restrict__ out) {
    size_t i = (size_t)blockIdx.x * blockDim.x + threadIdx.x;   // float4 index
    if (i >= (size_t)E_ROWS * (OUT_N / 4)) return;
    int c = (int)((i & (OUT_N / 4 - 1)) * 4);
    float4 v  = ((const float4*)g_y2)[i];
    float4 sc = *(const float4*)(g_scale2 + c);
    float4 sh = *(const float4*)(g_shift2 + c);
    v.x = fmaf(v.x, sc.x, sh.x);
    v.y = fmaf(v.y, sc.y, sh.y);
    v.z = fmaf(v.z, sc.z, sh.z);
    v.w = fmaf(v.w, sc.w, sh.w);
    ((float4*)out)[i] = v;
}

// ============================================================================
// kernel_launch
// ============================================================================
extern "C" void kernel_launch(void* const* d_in, const int* in_sizes, int n_in,
                              void* d_out, int out_size) {
    (void)in_sizes; (void)n_in; (void)out_size;
    const float* src   = (const float*)d_in[0];
    const float* dst   = (const float*)d_in[1];
    const float* edge  = (const float*)d_in[2];
    const float* u     = (const float*)d_in[3];
    const int*   batch = (const int*)d_in[4];     // int32 (JAX x64 disabled)
    const float* W1    = (const float*)d_in[5];
    const float* g1    = (const float*)d_in[6];
    const float* b1    = (const float*)d_in[7];
    const float* W2    = (const float*)d_in[8];
    const float* g2    = (const float*)d_in[9];
    const float* b2    = (const float*)d_in[10];
    float* out = (float*)d_out;

    cudaFuncSetAttribute(k_gemm<0>, cudaFuncAttributeMaxDynamicSharedMemorySize, SMEM_TOTAL);
    cudaFuncSetAttribute(k_gemm<1>, cudaFuncAttributeMaxDynamicSharedMemorySize, SMEM_TOTAL);

    k_prep<<<(K1 * OUT_N + K2 * OUT_N + 255) / 256, 256>>>(W1, W2);
    k_gemm<0><<<N_TILES, THREADS, SMEM_TOTAL>>>(src, dst, edge, u, batch);
    k_reduce<<<1, 256>>>(g1, b1, 0);
    k_gemm<1><<<N_TILES, THREADS, SMEM_TOTAL>>>(src, dst, edge, u, batch);
    k_reduce<<<1, 256>>>(g2, b2, 1);
    k_finalize<<<(int)(((size_t)E_ROWS * (OUT_N / 4) + 255) / 256), 256>>>(out);
}

// round 10
// speedup vs baseline: 2.5765x; 2.5765x over previous
#include <cuda_runtime.h>
#include <cstdint>
#include <cstddef>

// ============================================================================
// Problem constants
// ============================================================================
#define E_ROWS   500000
#define OUT_N    256
#define K1       384        // 2*128 + 64 + 64
#define K2       256
#define D_NODE   128
#define D_EDGE   64
#define D_U      64
#define BN_EPS   1e-5

#define TILE_M   128
#define BK       32
#define N_TILES  ((E_ROWS + TILE_M - 1) / TILE_M)   // 3907
#define THREADS  512

// SMEM padded strides (floats) — proven conflict-free for fragment LDS
#define ASTR 36      // A: 128 rows x 32 cols, stride 36
#define BSTR 264     // B: 32 rows x 256 cols, stride 264

// SMEM layout (bytes)
#define SM_AFF   0                       // 512 floats (scale|shift) for layer 1
#define SM_A0    2048
#define SM_A1    (SM_A0 + 128*ASTR*4)    // 20480
#define SM_B0    (SM_A1 + 128*ASTR*4)    // 38912
#define SM_B1    (SM_B0 + BK*BSTR*4)     // 72704
#define SMEM_TOTAL (SM_B1 + BK*BSTR*4)   // 106496

// ============================================================================
// Scratch (static __device__ — no allocations allowed)
// ============================================================================
__device__ __align__(16) float g_y1[(size_t)E_ROWS * OUT_N];   // 512 MB
__device__ __align__(16) float g_y2[(size_t)E_ROWS * OUT_N];   // 512 MB
__device__ __align__(16) float g_W1r[K1 * OUT_N];              // tf32-rounded W1 [384][256]
__device__ __align__(16) float g_W2r[K2 * OUT_N];              // tf32-rounded W2 [256][256]
__device__ __align__(16) float g_part_sum[4096 * OUT_N];
__device__ __align__(16) float g_part_sq [4096 * OUT_N];
__device__ __align__(16) float g_scale1[OUT_N], g_shift1[OUT_N];
__device__ __align__(16) float g_scale2[OUT_N], g_shift2[OUT_N];

// ============================================================================
// Helpers
// ============================================================================
__device__ __forceinline__ float to_tf32(float x) {
    uint32_t r;
    asm("cvt.rna.tf32.f32 %0, %1;" : "=r"(r) : "f"(x));
    return __uint_as_float(r);
}
__device__ __forceinline__ uint32_t to_tf32_u(float x) {
    uint32_t r;
    asm("cvt.rna.tf32.f32 %0, %1;" : "=r"(r) : "f"(x));
    return r;
}
__device__ __forceinline__ uint32_t smem_to_u32(const void* p) {
    uint32_t a;
    asm("{ .reg .u64 t; cvta.to.shared.u64 t, %1; cvt.u32.u64 %0, t; }" : "=r"(a) : "l"(p));
    return a;
}
__device__ __forceinline__ void cp16(uint32_t dst_smem, const void* src) {
    asm volatile("cp.async.cg.shared.global [%0], [%1], 16;"
                 :: "r"(dst_smem), "l"(src) : "memory");
}
__device__ __forceinline__ void cp_commit() {
    asm volatile("cp.async.commit_group;" ::: "memory");
}

// m16n8k8 tf32 MMA: D += A(16x8, row) * B(8x8, col)
__device__ __forceinline__ void mma8(float* c, const uint32_t* a, uint32_t b0, uint32_t b1) {
    asm volatile(
        "mma.sync.aligned.m16n8k8.row.col.f32.tf32.tf32.f32 "
        "{%0,%1,%2,%3}, {%4,%5,%6,%7}, {%8,%9}, {%0,%1,%2,%3};"
        : "+f"(c[0]), "+f"(c[1]), "+f"(c[2]), "+f"(c[3])
        : "r"(a[0]), "r"(a[1]), "r"(a[2]), "r"(a[3]), "r"(b0), "r"(b1));
}

// ============================================================================
// Kernel 1: tf32-round weights (keep original [K][N] layout)
// ============================================================================
__global__ void k_prep(const float* __restrict__ W1, const float* __restrict__ W2) {
    int i = blockIdx.x * blockDim.x + threadIdx.x;
    if (i < K1 * OUT_N)            g_W1r[i] = to_tf32(W1[i]);
    else if (i - K1 * OUT_N < K2 * OUT_N) {
        int j = i - K1 * OUT_N;
        g_W2r[j] = to_tf32(W2[j]);
    }
}

// ============================================================================
// Tile loaders (cp.async into padded SMEM). batch is int32.
// ============================================================================
template <int LAYER>
__device__ __forceinline__ void load_tiles(
    char* smem, uint32_t sbase, int buf, int kc, int tid, int m0,
    const float* __restrict__ src, const float* __restrict__ dst,
    const float* __restrict__ edge, const float* __restrict__ u,
    const int* __restrict__ batch)
{
    const int k0 = kc * BK;
    const uint32_t aoff = sbase + (buf ? SM_A1 : SM_A0);
    const uint32_t boff = sbase + (buf ? SM_B1 : SM_B0);

    // ---- A tile: 128 rows x 32 cols = 1024 x 16B chunks, 2 per thread ----
    #pragma unroll
    for (int i = 0; i < 2; i++) {
        int id = tid + i * THREADS;
        int r = id >> 3;
        int c4 = (id & 7) * 4;
        long long grow = m0 + r;
        if (grow >= E_ROWS) grow = E_ROWS - 1;
        const float* sp;
        if (LAYER == 0) {
            if (k0 < 128)       sp = src  + grow * D_NODE + (k0      ) + c4;
            else if (k0 < 256)  sp = dst  + grow * D_NODE + (k0 - 128) + c4;
            else if (k0 < 320)  sp = edge + grow * D_EDGE + (k0 - 256) + c4;
            else {
                long long b = (long long)batch[grow];
                sp = u + b * D_U + (k0 - 320) + c4;
            }
        } else {
            sp = g_y1 + grow * (long long)OUT_N + k0 + c4;
        }
        cp16(aoff + (uint32_t)(r * ASTR + c4) * 4u, sp);
    }

    // ---- B tile: 32 rows x 256 cols = 2048 x 16B chunks, 4 per thread ----
    const float* __restrict__ W = (LAYER == 0) ? g_W1r : g_W2r;
    #pragma unroll
    for (int i = 0; i < 4; i++) {
        int id = tid + i * THREADS;
        int r = id >> 6;
        int c = (id & 63) * 4;
        cp16(boff + (uint32_t)(r * BSTR + c) * 4u, W + (size_t)(k0 + r) * OUT_N + c);
    }
    cp_commit();
}

// ============================================================================
// Kernel 2/4: GEMM (128x256 CTA tile, 32x64 warp tile, m16n8k8 tf32)
//   LAYER 0: A = concat(src,dest,edge,u[batch]) -> g_y1 + stats partials
//   LAYER 1: A = relu(bn1(g_y1)) (fused at fragment load) -> g_y2 + partials
// ============================================================================
template <int LAYER>
__global__ __launch_bounds__(THREADS, 1) void k_gemm(
    const float* __restrict__ src, const float* __restrict__ dst,
    const float* __restrict__ edge, const float* __restrict__ u,
    const int* __restrict__ batch)
{
    extern __shared__ char smem[];
    const uint32_t sbase = smem_to_u32(smem);
    const int tid   = threadIdx.x;
    const int wid   = tid >> 5;
    const int lane  = tid & 31;
    const int g     = lane >> 2;       // 0..7
    const int t     = lane & 3;        // 0..3
    const int warp_m = wid & 3;        // 4 row-warps of 32 rows
    const int warp_n = wid >> 2;       // 4 col-warps of 64 cols
    const int m0 = blockIdx.x * TILE_M;
    const int NK = (LAYER == 0) ? (K1 / BK) : (K2 / BK);

    float* aff = (float*)(smem + SM_AFF);
    if (LAYER == 1) {
        if (tid < 256)      aff[tid]       = g_scale1[tid];
        else                aff[tid]       = g_shift1[tid - 256];  // aff[256..511]
        __syncthreads();
    }

    float acc[2][8][4];
    #pragma unroll
    for (int mt = 0; mt < 2; mt++)
        #pragma unroll
        for (int nt = 0; nt < 8; nt++)
            #pragma unroll
            for (int j = 0; j < 4; j++) acc[mt][nt][j] = 0.f;

    load_tiles<LAYER>(smem, sbase, 0, 0, tid, m0, src, dst, edge, u, batch);

    for (int kc = 0; kc < NK; kc++) {
        const int buf = kc & 1;
        if (kc + 1 < NK) {
            load_tiles<LAYER>(smem, sbase, buf ^ 1, kc + 1, tid, m0, src, dst, edge, u, batch);
            asm volatile("cp.async.wait_group 1;" ::: "memory");
        } else {
            asm volatile("cp.async.wait_group 0;" ::: "memory");
        }
        __syncthreads();

        const float* As = (const float*)(smem + (buf ? SM_A1 : SM_A0));
        const float* Bs = (const float*)(smem + (buf ? SM_B1 : SM_B0));
        const float* Ap = As + (warp_m * 32 + g) * ASTR + t;
        const float* Bp = Bs + t * BSTR + warp_n * 64 + g;

        #pragma unroll
        for (int ks = 0; ks < 4; ks++) {
            // A fragments: a0(g,t) a1(g+8,t) a2(g,t+4) a3(g+8,t+4)
            float af[2][4];
            #pragma unroll
            for (int mt = 0; mt < 2; mt++) {
                af[mt][0] = Ap[(mt * 16    ) * ASTR + ks * 8    ];
                af[mt][1] = Ap[(mt * 16 + 8) * ASTR + ks * 8    ];
                af[mt][2] = Ap[(mt * 16    ) * ASTR + ks * 8 + 4];
                af[mt][3] = Ap[(mt * 16 + 8) * ASTR + ks * 8 + 4];
            }
            if (LAYER == 1) {
                const int kk = kc * 32 + ks * 8;
                float s0 = aff[kk + t],       h0 = aff[256 + kk + t];
                float s4 = aff[kk + t + 4],   h4 = aff[256 + kk + t + 4];
                #pragma unroll
                for (int mt = 0; mt < 2; mt++) {
                    af[mt][0] = fmaxf(fmaf(af[mt][0], s0, h0), 0.f);
                    af[mt][1] = fmaxf(fmaf(af[mt][1], s0, h0), 0.f);
                    af[mt][2] = fmaxf(fmaf(af[mt][2], s4, h4), 0.f);
                    af[mt][3] = fmaxf(fmaf(af[mt][3], s4, h4), 0.f);
                }
            }
            uint32_t ua[2][4];
            #pragma unroll
            for (int mt = 0; mt < 2; mt++)
                #pragma unroll
                for (int j = 0; j < 4; j++) ua[mt][j] = to_tf32_u(af[mt][j]);

            // B fragments: b0(k=t, n=g), b1(k=t+4, n=g) — pre-rounded in k_prep
            uint32_t b0[8], b1[8];
            #pragma unroll
            for (int nt = 0; nt < 8; nt++) {
                b0[nt] = __float_as_uint(Bp[(ks * 8    ) * BSTR + nt * 8]);
                b1[nt] = __float_as_uint(Bp[(ks * 8 + 4) * BSTR + nt * 8]);
            }
            #pragma unroll
            for (int mt = 0; mt < 2; mt++)
                #pragma unroll
                for (int nt = 0; nt < 8; nt++)
                    mma8(acc[mt][nt], ua[mt], b0[nt], b1[nt]);
        }
        __syncthreads();
    }

    // ================= Epilogue: store y + column sum/sumsq partials ========
    float* __restrict__ ybuf = (LAYER == 0) ? g_y1 : g_y2;
    float* sm_ps = (float*)(smem + SM_A0);          // [4][256]
    float* sm_sq = sm_ps + 4 * OUT_N;               // [4][256]

    const int r_base = m0 + warp_m * 32 + g;

    #pragma unroll
    for (int nt = 0; nt < 8; nt++) {
        const int col = warp_n * 64 + nt * 8 + 2 * t;
        float v0 = 0.f, v1 = 0.f, q0 = 0.f, q1 = 0.f;
        #pragma unroll
        for (int mt = 0; mt < 2; mt++) {
            const long long r1 = r_base + mt * 16;
            const long long r2 = r1 + 8;
            float c0 = acc[mt][nt][0], c1 = acc[mt][nt][1];
            float c2 = acc[mt][nt][2], c3 = acc[mt][nt][3];
            if (r1 < E_ROWS) {
                *(float2*)(ybuf + r1 * OUT_N + col) = make_float2(c0, c1);
                v0 += c0; v1 += c1; q0 += c0 * c0; q1 += c1 * c1;
            }
            if (r2 < E_ROWS) {
                *(float2*)(ybuf + r2 * OUT_N + col) = make_float2(c2, c3);
                v0 += c2; v1 += c3; q0 += c2 * c2; q1 += c3 * c3;
            }
        }
        // reduce over the 8 lanes sharing t (g spans lane bits 2..4)
        #pragma unroll
        for (int o = 4; o < 32; o <<= 1) {
            v0 += __shfl_xor_sync(0xffffffffu, v0, o);
            v1 += __shfl_xor_sync(0xffffffffu, v1, o);
            q0 += __shfl_xor_sync(0xffffffffu, q0, o);
            q1 += __shfl_xor_sync(0xffffffffu, q1, o);
        }
        if (g == 0) {
            sm_ps[warp_m * OUT_N + col]     = v0;
            sm_ps[warp_m * OUT_N + col + 1] = v1;
            sm_sq[warp_m * OUT_N + col]     = q0;
            sm_sq[warp_m * OUT_N + col + 1] = q1;
        }
    }
    __syncthreads();

    if (tid < OUT_N) {
        float s = 0.f, q = 0.f;
        #pragma unroll
        for (int wm = 0; wm < 4; wm++) {
            s += sm_ps[wm * OUT_N + tid];
            q += sm_sq[wm * OUT_N + tid];
        }
        g_part_sum[(size_t)blockIdx.x * OUT_N + tid] = s;
        g_part_sq [(size_t)blockIdx.x * OUT_N + tid] = q;
    }
}

// ============================================================================
// Kernel 3/5: finalize BN stats — PARALLEL deterministic reduction.
// One CTA per output column (256 CTAs x 256 threads). Each thread strides
// over tiles (fixed order), partials tree-reduced in shared double (fixed
// order -> deterministic). Replaces the single-CTA serial loop that was
// latency-bound at ~1 ms per call.
// ============================================================================
__global__ __launch_bounds__(256) void k_reduce(
    const float* __restrict__ g, const float* __restrict__ b, int layer)
{
    const int c   = blockIdx.x;    // column 0..255
    const int tid = threadIdx.x;   // 0..255

    double s = 0.0, q = 0.0;
    for (int t = tid; t < N_TILES; t += 256) {
        s += (double)g_part_sum[(size_t)t * OUT_N + c];
        q += (double)g_part_sq [(size_t)t * OUT_N + c];
    }

    __shared__ double ss[256];
    __shared__ double sq[256];
    ss[tid] = s; sq[tid] = q;
    __syncthreads();
    #pragma unroll
    for (int o = 128; o > 0; o >>= 1) {
        if (tid < o) { ss[tid] += ss[tid + o]; sq[tid] += sq[tid + o]; }
        __syncthreads();
    }

    if (tid == 0) {
        double m   = ss[0] / (double)E_ROWS;
        double var = sq[0] / (double)E_ROWS - m * m;
        float rstd = (float)(1.0 / sqrt(var + BN_EPS));
        float scale = g[c] * rstd;
        float shift = b[c] - (float)m * scale;
        if (layer == 0) { g_scale1[c] = scale; g_shift1[c] = shift; }
        else            { g_scale2[c] = scale; g_shift2[c] = shift; }
    }
}

// ============================================================================
// Kernel 6: out = y2 * scale2 + shift2
// ============================================================================
__global__ void k_finalize(float* __restrict__ out) {
    size_t i = (size_t)blockIdx.x * blockDim.x + threadIdx.x;   // float4 index
    if (i >= (size_t)E_ROWS * (OUT_N / 4)) return;
    int c = (int)((i & (OUT_N / 4 - 1)) * 4);
    float4 v  = ((const float4*)g_y2)[i];
    float4 sc = *(const float4*)(g_scale2 + c);
    float4 sh = *(const float4*)(g_shift2 + c);
    v.x = fmaf(v.x, sc.x, sh.x);
    v.y = fmaf(v.y, sc.y, sh.y);
    v.z = fmaf(v.z, sc.z, sh.z);
    v.w = fmaf(v.w, sc.w, sh.w);
    ((float4*)out)[i] = v;
}

// ============================================================================
// kernel_launch
// ============================================================================
extern "C" void kernel_launch(void* const* d_in, const int* in_sizes, int n_in,
                              void* d_out, int out_size) {
    (void)in_sizes; (void)n_in; (void)out_size;
    const float* src   = (const float*)d_in[0];
    const float* dst   = (const float*)d_in[1];
    const float* edge  = (const float*)d_in[2];
    const float* u     = (const float*)d_in[3];
    const int*   batch = (const int*)d_in[4];     // int32 (JAX x64 disabled)
    const float* W1    = (const float*)d_in[5];
    const float* g1    = (const float*)d_in[6];
    const float* b1    = (const float*)d_in[7];
    const float* W2    = (const float*)d_in[8];
    const float* g2    = (const float*)d_in[9];
    const float* b2    = (const float*)d_in[10];
    float* out = (float*)d_out;

    cudaFuncSetAttribute(k_gemm<0>, cudaFuncAttributeMaxDynamicSharedMemorySize, SMEM_TOTAL);
    cudaFuncSetAttribute(k_gemm<1>, cudaFuncAttributeMaxDynamicSharedMemorySize, SMEM_TOTAL);

    k_prep<<<(K1 * OUT_N + K2 * OUT_N + 255) / 256, 256>>>(W1, W2);
    k_gemm<0><<<N_TILES, THREADS, SMEM_TOTAL>>>(src, dst, edge, u, batch);
    k_reduce<<<OUT_N, 256>>>(g1, b1, 0);
    k_gemm<1><<<N_TILES, THREADS, SMEM_TOTAL>>>(src, dst, edge, u, batch);
    k_reduce<<<OUT_N, 256>>>(g2, b2, 1);
    k_finalize<<<(int)(((size_t)E_ROWS * (OUT_N / 4) + 255) / 256), 256>>>(out);
}

// round 12
// speedup vs baseline: 2.6474x; 1.0275x over previous
#include <cuda_runtime.h>
#include <cstdint>
#include <cstddef>

// ============================================================================
// Problem constants
// ============================================================================
#define E_ROWS   500000
#define OUT_N    256
#define K1       384        // 2*128 + 64 + 64
#define K2       256
#define D_NODE   128
#define D_EDGE   64
#define D_U      64
#define BN_EPS   1e-5

#define TILE_M   128
#define BK       32
#define N_TILES  ((E_ROWS + TILE_M - 1) / TILE_M)   // 3907
#define THREADS  256        // 8 warps: 2 warp_m x 4 warp_n, 64x64 warp tiles

// SMEM padded strides (floats) — conflict-free for fragment LDS
#define ASTR 36      // A: 128 rows x 32 cols, stride 36
#define BSTR 264     // B: 32 rows x 256 cols, stride 264

// SMEM layout (bytes)
#define SM_AFF   0                       // 512 floats (scale|shift) for layer 1
#define SM_A0    2048
#define SM_A1    (SM_A0 + 128*ASTR*4)    // +18432
#define SM_B0    (SM_A1 + 128*ASTR*4)
#define SM_B1    (SM_B0 + BK*BSTR*4)     // +33792
#define SMEM_TOTAL (SM_B1 + BK*BSTR*4)   // 106496

// ============================================================================
// Scratch (static __device__ — no allocations allowed)
// ============================================================================
__device__ __align__(16) float g_y1[(size_t)E_ROWS * OUT_N];   // 512 MB
__device__ __align__(16) float g_y2[(size_t)E_ROWS * OUT_N];   // 512 MB
__device__ __align__(16) float g_W1r[K1 * OUT_N];              // tf32-rounded W1
__device__ __align__(16) float g_W2r[K2 * OUT_N];              // tf32-rounded W2
__device__ __align__(16) float g_part_sum[4096 * OUT_N];
__device__ __align__(16) float g_part_sq [4096 * OUT_N];
__device__ __align__(16) float g_scale1[OUT_N], g_shift1[OUT_N];
__device__ __align__(16) float g_scale2[OUT_N], g_shift2[OUT_N];

// ============================================================================
// Helpers
// ============================================================================
__device__ __forceinline__ float to_tf32(float x) {
    uint32_t r;
    asm("cvt.rna.tf32.f32 %0, %1;" : "=r"(r) : "f"(x));
    return __uint_as_float(r);
}
__device__ __forceinline__ uint32_t to_tf32_u(float x) {
    uint32_t r;
    asm("cvt.rna.tf32.f32 %0, %1;" : "=r"(r) : "f"(x));
    return r;
}
__device__ __forceinline__ uint32_t smem_to_u32(const void* p) {
    uint32_t a;
    asm("{ .reg .u64 t; cvta.to.shared.u64 t, %1; cvt.u32.u64 %0, t; }" : "=r"(a) : "l"(p));
    return a;
}
__device__ __forceinline__ void cp16(uint32_t dst_smem, const void* src) {
    asm volatile("cp.async.cg.shared.global [%0], [%1], 16;"
                 :: "r"(dst_smem), "l"(src) : "memory");
}
__device__ __forceinline__ void cp_commit() {
    asm volatile("cp.async.commit_group;" ::: "memory");
}

// m16n8k8 tf32 MMA: D += A(16x8, row) * B(8x8, col)
__device__ __forceinline__ void mma8(float* c, const uint32_t* a, uint32_t b0, uint32_t b1) {
    asm volatile(
        "mma.sync.aligned.m16n8k8.row.col.f32.tf32.tf32.f32 "
        "{%0,%1,%2,%3}, {%4,%5,%6,%7}, {%8,%9}, {%0,%1,%2,%3};"
        : "+f"(c[0]), "+f"(c[1]), "+f"(c[2]), "+f"(c[3])
        : "r"(a[0]), "r"(a[1]), "r"(a[2]), "r"(a[3]), "r"(b0), "r"(b1));
}

// ============================================================================
// Kernel 1: tf32-round weights (keep original [K][N] layout)
// ============================================================================
__global__ void k_prep(const float* __restrict__ W1, const float* __restrict__ W2) {
    int i = blockIdx.x * blockDim.x + threadIdx.x;
    if (i < K1 * OUT_N)            g_W1r[i] = to_tf32(W1[i]);
    else if (i - K1 * OUT_N < K2 * OUT_N) {
        int j = i - K1 * OUT_N;
        g_W2r[j] = to_tf32(W2[j]);
    }
}

// ============================================================================
// Tile loaders (cp.async into padded SMEM). batch is int32.
// ============================================================================
template <int LAYER>
__device__ __forceinline__ void load_tiles(
    char* smem, uint32_t sbase, int buf, int kc, int tid, int m0,
    const float* __restrict__ src, const float* __restrict__ dst,
    const float* __restrict__ edge, const float* __restrict__ u,
    const int* __restrict__ batch)
{
    const int k0 = kc * BK;
    const uint32_t aoff = sbase + (buf ? SM_A1 : SM_A0);
    const uint32_t boff = sbase + (buf ? SM_B1 : SM_B0);

    // ---- A tile: 128 rows x 32 cols = 1024 x 16B chunks, 4 per thread ----
    #pragma unroll
    for (int i = 0; i < 4; i++) {
        int id = tid + i * THREADS;
        int r = id >> 3;
        int c4 = (id & 7) * 4;
        long long grow = m0 + r;
        if (grow >= E_ROWS) grow = E_ROWS - 1;
        const float* sp;
        if (LAYER == 0) {
            if (k0 < 128)       sp = src  + grow * D_NODE + (k0      ) + c4;
            else if (k0 < 256)  sp = dst  + grow * D_NODE + (k0 - 128) + c4;
            else if (k0 < 320)  sp = edge + grow * D_EDGE + (k0 - 256) + c4;
            else {
                long long b = (long long)batch[grow];
                sp = u + b * D_U + (k0 - 320) + c4;
            }
        } else {
            sp = g_y1 + grow * (long long)OUT_N + k0 + c4;
        }
        cp16(aoff + (uint32_t)(r * ASTR + c4) * 4u, sp);
    }

    // ---- B tile: 32 rows x 256 cols = 2048 x 16B chunks, 8 per thread ----
    const float* __restrict__ W = (LAYER == 0) ? g_W1r : g_W2r;
    #pragma unroll
    for (int i = 0; i < 8; i++) {
        int id = tid + i * THREADS;
        int r = id >> 6;
        int c = (id & 63) * 4;
        cp16(boff + (uint32_t)(r * BSTR + c) * 4u, W + (size_t)(k0 + r) * OUT_N + c);
    }
    cp_commit();
}

// ============================================================================
// Kernel 2/4: GEMM (128x256 CTA tile, 64x64 warp tile, m16n8k8 tf32)
//   LAYER 0: A = concat(src,dest,edge,u[batch]) -> g_y1 + stats partials
//   LAYER 1: A = relu(bn1(g_y1)) (fused at fragment load) -> g_y2 + partials
// ============================================================================
template <int LAYER>
__global__ __launch_bounds__(THREADS, 1) void k_gemm(
    const float* __restrict__ src, const float* __restrict__ dst,
    const float* __restrict__ edge, const float* __restrict__ u,
    const int* __restrict__ batch)
{
    extern __shared__ char smem[];
    const uint32_t sbase = smem_to_u32(smem);
    const int tid   = threadIdx.x;
    const int wid   = tid >> 5;
    const int lane  = tid & 31;
    const int g     = lane >> 2;       // 0..7
    const int t     = lane & 3;        // 0..3
    const int warp_m = wid & 1;        // 2 row-warps of 64 rows
    const int warp_n = wid >> 1;       // 4 col-warps of 64 cols
    const int m0 = blockIdx.x * TILE_M;
    const int NK = (LAYER == 0) ? (K1 / BK) : (K2 / BK);

    float* aff = (float*)(smem + SM_AFF);
    if (LAYER == 1) {
        aff[tid]       = g_scale1[tid];
        aff[256 + tid] = g_shift1[tid];
        __syncthreads();
    }

    float acc[4][8][4];
    #pragma unroll
    for (int mt = 0; mt < 4; mt++)
        #pragma unroll
        for (int nt = 0; nt < 8; nt++)
            #pragma unroll
            for (int j = 0; j < 4; j++) acc[mt][nt][j] = 0.f;

    load_tiles<LAYER>(smem, sbase, 0, 0, tid, m0, src, dst, edge, u, batch);

    for (int kc = 0; kc < NK; kc++) {
        const int buf = kc & 1;
        if (kc + 1 < NK) {
            load_tiles<LAYER>(smem, sbase, buf ^ 1, kc + 1, tid, m0, src, dst, edge, u, batch);
            asm volatile("cp.async.wait_group 1;" ::: "memory");
        } else {
            asm volatile("cp.async.wait_group 0;" ::: "memory");
        }
        __syncthreads();

        const float* As = (const float*)(smem + (buf ? SM_A1 : SM_A0));
        const float* Bs = (const float*)(smem + (buf ? SM_B1 : SM_B0));
        const float* Ap = As + (warp_m * 64 + g) * ASTR + t;
        const float* Bp = Bs + t * BSTR + warp_n * 64 + g;

        #pragma unroll
        for (int ks = 0; ks < 4; ks++) {
            // A fragments: per mt: a0(g,t) a1(g+8,t) a2(g,t+4) a3(g+8,t+4)
            float af[4][4];
            #pragma unroll
            for (int mt = 0; mt < 4; mt++) {
                af[mt][0] = Ap[(mt * 16    ) * ASTR + ks * 8    ];
                af[mt][1] = Ap[(mt * 16 + 8) * ASTR + ks * 8    ];
                af[mt][2] = Ap[(mt * 16    ) * ASTR + ks * 8 + 4];
                af[mt][3] = Ap[(mt * 16 + 8) * ASTR + ks * 8 + 4];
            }
            if (LAYER == 1) {
                const int kk = kc * 32 + ks * 8;
                float s0 = aff[kk + t],       h0 = aff[256 + kk + t];
                float s4 = aff[kk + t + 4],   h4 = aff[256 + kk + t + 4];
                #pragma unroll
                for (int mt = 0; mt < 4; mt++) {
                    af[mt][0] = fmaxf(fmaf(af[mt][0], s0, h0), 0.f);
                    af[mt][1] = fmaxf(fmaf(af[mt][1], s0, h0), 0.f);
                    af[mt][2] = fmaxf(fmaf(af[mt][2], s4, h4), 0.f);
                    af[mt][3] = fmaxf(fmaf(af[mt][3], s4, h4), 0.f);
                }
            }
            uint32_t ua[4][4];
            #pragma unroll
            for (int mt = 0; mt < 4; mt++)
                #pragma unroll
                for (int j = 0; j < 4; j++) ua[mt][j] = to_tf32_u(af[mt][j]);

            // B fragments: b0(k=t, n=g), b1(k=t+4, n=g) — pre-rounded in k_prep
            uint32_t b0[8], b1[8];
            #pragma unroll
            for (int nt = 0; nt < 8; nt++) {
                b0[nt] = __float_as_uint(Bp[(ks * 8    ) * BSTR + nt * 8]);
                b1[nt] = __float_as_uint(Bp[(ks * 8 + 4) * BSTR + nt * 8]);
            }
            #pragma unroll
            for (int mt = 0; mt < 4; mt++)
                #pragma unroll
                for (int nt = 0; nt < 8; nt++)
                    mma8(acc[mt][nt], ua[mt], b0[nt], b1[nt]);
        }
        __syncthreads();
    }

    // ================= Epilogue: store y + column sum/sumsq partials ========
    float* __restrict__ ybuf = (LAYER == 0) ? g_y1 : g_y2;
    float* sm_ps = (float*)(smem + SM_A0);          // [2][256]
    float* sm_sq = sm_ps + 2 * OUT_N;               // [2][256]

    const int r_base = m0 + warp_m * 64 + g;

    #pragma unroll
    for (int nt = 0; nt < 8; nt++) {
        const int col = warp_n * 64 + nt * 8 + 2 * t;
        float v0 = 0.f, v1 = 0.f, q0 = 0.f, q1 = 0.f;
        #pragma unroll
        for (int mt = 0; mt < 4; mt++) {
            const long long r1 = r_base + mt * 16;
            const long long r2 = r1 + 8;
            float c0 = acc[mt][nt][0], c1 = acc[mt][nt][1];
            float c2 = acc[mt][nt][2], c3 = acc[mt][nt][3];
            if (r1 < E_ROWS) {
                *(float2*)(ybuf + r1 * OUT_N + col) = make_float2(c0, c1);
                v0 += c0; v1 += c1; q0 += c0 * c0; q1 += c1 * c1;
            }
            if (r2 < E_ROWS) {
                *(float2*)(ybuf + r2 * OUT_N + col) = make_float2(c2, c3);
                v0 += c2; v1 += c3; q0 += c2 * c2; q1 += c3 * c3;
            }
        }
        // reduce over the 8 lanes sharing t (g spans lane bits 2..4)
        #pragma unroll
        for (int o = 4; o < 32; o <<= 1) {
            v0 += __shfl_xor_sync(0xffffffffu, v0, o);
            v1 += __shfl_xor_sync(0xffffffffu, v1, o);
            q0 += __shfl_xor_sync(0xffffffffu, q0, o);
            q1 += __shfl_xor_sync(0xffffffffu, q1, o);
        }
        if (g == 0) {
            sm_ps[warp_m * OUT_N + col]     = v0;
            sm_ps[warp_m * OUT_N + col + 1] = v1;
            sm_sq[warp_m * OUT_N + col]     = q0;
            sm_sq[warp_m * OUT_N + col + 1] = q1;
        }
    }
    __syncthreads();

    {
        float s = sm_ps[tid] + sm_ps[OUT_N + tid];
        float q = sm_sq[tid] + sm_sq[OUT_N + tid];
        g_part_sum[(size_t)blockIdx.x * OUT_N + tid] = s;
        g_part_sq [(size_t)blockIdx.x * OUT_N + tid] = q;
    }
}

// ============================================================================
// Kernel 3/5: finalize BN stats — parallel deterministic reduction.
// One CTA per output column (256 CTAs x 256 threads).
// ============================================================================
__global__ __launch_bounds__(256) void k_reduce(
    const float* __restrict__ g, const float* __restrict__ b, int layer)
{
    const int c   = blockIdx.x;    // column 0..255
    const int tid = threadIdx.x;   // 0..255

    double s = 0.0, q = 0.0;
    for (int t = tid; t < N_TILES; t += 256) {
        s += (double)g_part_sum[(size_t)t * OUT_N + c];
        q += (double)g_part_sq [(size_t)t * OUT_N + c];
    }

    __shared__ double ss[256];
    __shared__ double sq[256];
    ss[tid] = s; sq[tid] = q;
    __syncthreads();
    #pragma unroll
    for (int o = 128; o > 0; o >>= 1) {
        if (tid < o) { ss[tid] += ss[tid + o]; sq[tid] += sq[tid + o]; }
        __syncthreads();
    }

    if (tid == 0) {
        double m   = ss[0] / (double)E_ROWS;
        double var = sq[0] / (double)E_ROWS - m * m;
        float rstd = (float)(1.0 / sqrt(var + BN_EPS));
        float scale = g[c] * rstd;
        float shift = b[c] - (float)m * scale;
        if (layer == 0) { g_scale1[c] = scale; g_shift1[c] = shift; }
        else            { g_scale2[c] = scale; g_shift2[c] = shift; }
    }
}

// ============================================================================
// Kernel 6: out = y2 * scale2 + shift2
// ============================================================================
__global__ void k_finalize(float* __restrict__ out) {
    size_t i = (size_t)blockIdx.x * blockDim.x + threadIdx.x;   // float4 index
    if (i >= (size_t)E_ROWS * (OUT_N / 4)) return;
    int c = (int)((i & (OUT_N / 4 - 1)) * 4);
    float4 v  = ((const float4*)g_y2)[i];
    float4 sc = *(const float4*)(g_scale2 + c);
    float4 sh = *(const float4*)(g_shift2 + c);
    v.x = fmaf(v.x, sc.x, sh.x);
    v.y = fmaf(v.y, sc.y, sh.y);
    v.z = fmaf(v.z, sc.z, sh.z);
    v.w = fmaf(v.w, sc.w, sh.w);
    ((float4*)out)[i] = v;
}

// ============================================================================
// kernel_launch
// ============================================================================
extern "C" void kernel_launch(void* const* d_in, const int* in_sizes, int n_in,
                              void* d_out, int out_size) {
    (void)in_sizes; (void)n_in; (void)out_size;
    const float* src   = (const float*)d_in[0];
    const float* dst   = (const float*)d_in[1];
    const float* edge  = (const float*)d_in[2];
    const float* u     = (const float*)d_in[3];
    const int*   batch = (const int*)d_in[4];     // int32 (JAX x64 disabled)
    const float* W1    = (const float*)d_in[5];
    const float* g1    = (const float*)d_in[6];
    const float* b1    = (const float*)d_in[7];
    const float* W2    = (const float*)d_in[8];
    const float* g2    = (const float*)d_in[9];
    const float* b2    = (const float*)d_in[10];
    float* out = (float*)d_out;

    cudaFuncSetAttribute(k_gemm<0>, cudaFuncAttributeMaxDynamicSharedMemorySize, SMEM_TOTAL);
    cudaFuncSetAttribute(k_gemm<1>, cudaFuncAttributeMaxDynamicSharedMemorySize, SMEM_TOTAL);

    k_prep<<<(K1 * OUT_N + K2 * OUT_N + 255) / 256, 256>>>(W1, W2);
    k_gemm<0><<<N_TILES, THREADS, SMEM_TOTAL>>>(src, dst, edge, u, batch);
    k_reduce<<<OUT_N, 256>>>(g1, b1, 0);
    k_gemm<1><<<N_TILES, THREADS, SMEM_TOTAL>>>(src, dst, edge, u, batch);
    k_reduce<<<OUT_N, 256>>>(g2, b2, 1);
    k_finalize<<<(int)(((size_t)E_ROWS * (OUT_N / 4) + 255) / 256), 256>>>(out);
}

// round 16
// speedup vs baseline: 3.1647x; 1.1954x over previous
#include <cuda_runtime.h>
#include <cuda_fp16.h>
#include <cstdint>
#include <cstddef>

// ============================================================================
// Problem constants
// ============================================================================
#define E_ROWS   500000
#define OUT_N    256
#define K1       384        // 2*128 + 64 + 64
#define K2       256
#define D_NODE   128
#define D_EDGE   64
#define D_U      64
#define BN_EPS   1e-5

#define TILE_M   128
#define BK       32
#define N_TILES  ((E_ROWS + TILE_M - 1) / TILE_M)   // 3907
#define THREADS  256        // 8 warps: 2 warp_m x 4 warp_n, 64x64 warp tiles

// SMEM strides
#define ASTR  36     // A tile: f32, 128 rows x 32 cols, stride 36 floats
#define BSTRH 40     // B tile: half, 256 n-rows x 32 k-halves, stride 40 halves (80 B)

// SMEM layout (bytes)
#define SM_AFF   0                        // 512 floats (scale|shift) for layer 1
#define SM_A0    2048
#define SM_A1    (SM_A0 + 128*ASTR*4)     // +18432
#define SM_B0    (SM_A1 + 128*ASTR*4)     // 38912
#define SM_B1    (SM_B0 + 256*BSTRH*2)    // +20480 -> 59392
#define SMEM_TOTAL (SM_B1 + 256*BSTRH*2)  // 79872

// ============================================================================
// Scratch (static __device__ — no allocations allowed)
// ============================================================================
__device__ __align__(16) float  g_y1[(size_t)E_ROWS * OUT_N];   // 512 MB
__device__ __align__(16) float  g_y2[(size_t)E_ROWS * OUT_N];   // 512 MB
__device__ __align__(16) __half g_W1h[OUT_N * K1];              // W1^T half [256][384]
__device__ __align__(16) __half g_W2h[OUT_N * K2];              // W2^T half [256][256]
__device__ __align__(16) float  g_part_sum[4096 * OUT_N];
__device__ __align__(16) float  g_part_sq [4096 * OUT_N];
__device__ __align__(16) float  g_scale1[OUT_N], g_shift1[OUT_N];
__device__ __align__(16) float  g_scale2[OUT_N], g_shift2[OUT_N];

// ============================================================================
// Helpers
// ============================================================================
__device__ __forceinline__ uint32_t smem_to_u32(const void* p) {
    uint32_t a;
    asm("{ .reg .u64 t; cvta.to.shared.u64 t, %1; cvt.u32.u64 %0, t; }" : "=r"(a) : "l"(p));
    return a;
}
__device__ __forceinline__ void cp16(uint32_t dst_smem, const void* src) {
    asm volatile("cp.async.cg.shared.global [%0], [%1], 16;"
                 :: "r"(dst_smem), "l"(src) : "memory");
}
__device__ __forceinline__ void cp_commit() {
    asm volatile("cp.async.commit_group;" ::: "memory");
}
__device__ __forceinline__ uint32_t pack_h2(float lo, float hi) {
    __half2 h = __float22half2_rn(make_float2(lo, hi));   // .x -> low half
    return *reinterpret_cast<uint32_t*>(&h);
}

// m16n8k16 fp16 MMA, f32 accum: D += A(16x16 row) * B(16x8 col)
__device__ __forceinline__ void mma16(float* c, const uint32_t* a, uint32_t b0, uint32_t b1) {
    asm volatile(
        "mma.sync.aligned.m16n8k16.row.col.f32.f16.f16.f32 "
        "{%0,%1,%2,%3}, {%4,%5,%6,%7}, {%8,%9}, {%0,%1,%2,%3};"
        : "+f"(c[0]), "+f"(c[1]), "+f"(c[2]), "+f"(c[3])
        : "r"(a[0]), "r"(a[1]), "r"(a[2]), "r"(a[3]), "r"(b0), "r"(b1));
}

// ============================================================================
// Kernel 1: transpose + halve weights: g_Wh[n][k] = half(W[k][n])
// ============================================================================
__global__ void k_prep(const float* __restrict__ W1, const float* __restrict__ W2) {
    int i = blockIdx.x * blockDim.x + threadIdx.x;
    if (i < K1 * OUT_N) {
        int k = i / OUT_N, n = i % OUT_N;
        g_W1h[n * K1 + k] = __float2half_rn(W1[i]);
    } else {
        int j = i - K1 * OUT_N;
        if (j < K2 * OUT_N) {
            int k = j / OUT_N, n = j % OUT_N;
            g_W2h[n * K2 + k] = __float2half_rn(W2[j]);
        }
    }
}

// ============================================================================
// Tile loaders (cp.async into SMEM). batch is int32.
//   A: f32, 128 rows x 32 cols (stride ASTR)
//   B: half, 256 n-rows x 32 k-halves (stride BSTRH), from pre-transposed Wh
// ============================================================================
template <int LAYER>
__device__ __forceinline__ void load_tiles(
    char* smem, uint32_t sbase, int buf, int kc, int tid, int m0,
    const float* __restrict__ src, const float* __restrict__ dst,
    const float* __restrict__ edge, const float* __restrict__ u,
    const int* __restrict__ batch)
{
    const int k0 = kc * BK;
    const uint32_t aoff = sbase + (buf ? SM_A1 : SM_A0);
    const uint32_t boff = sbase + (buf ? SM_B1 : SM_B0);

    // ---- A tile: 128 rows x 32 f32 = 1024 x 16B chunks, 4 per thread ----
    #pragma unroll
    for (int i = 0; i < 4; i++) {
        int id = tid + i * THREADS;
        int r = id >> 3;
        int c4 = (id & 7) * 4;
        long long grow = m0 + r;
        if (grow >= E_ROWS) grow = E_ROWS - 1;
        const float* sp;
        if (LAYER == 0) {
            if (k0 < 128)       sp = src  + grow * D_NODE + (k0      ) + c4;
            else if (k0 < 256)  sp = dst  + grow * D_NODE + (k0 - 128) + c4;
            else if (k0 < 320)  sp = edge + grow * D_EDGE + (k0 - 256) + c4;
            else {
                long long b = (long long)batch[grow];
                sp = u + b * D_U + (k0 - 320) + c4;
            }
        } else {
            sp = g_y1 + grow * (long long)OUT_N + k0 + c4;
        }
        cp16(aoff + (uint32_t)(r * ASTR + c4) * 4u, sp);
    }

    // ---- B tile: 256 n-rows x 32 halves = 64B/row = 1024 x 16B chunks ----
    const __half* __restrict__ Wh = (LAYER == 0) ? g_W1h : g_W2h;
    const int Ktot = (LAYER == 0) ? K1 : K2;
    #pragma unroll
    for (int i = 0; i < 4; i++) {
        int id = tid + i * THREADS;
        int n = id >> 2;
        int c8 = (id & 3) * 8;           // half offset within row
        cp16(boff + (uint32_t)(n * BSTRH + c8) * 2u,
             Wh + (size_t)n * Ktot + k0 + c8);
    }
    cp_commit();
}

// ============================================================================
// Kernel 2/4: GEMM (128x256 CTA tile, 64x64 warp tile, m16n8k16 fp16)
//   LAYER 0: A = concat(src,dest,edge,u[batch]) -> g_y1 + stats partials
//   LAYER 1: A = relu(bn1(g_y1)) (fused at fragment load) -> g_y2 + partials
// ============================================================================
template <int LAYER>
__global__ __launch_bounds__(THREADS, 1) void k_gemm(
    const float* __restrict__ src, const float* __restrict__ dst,
    const float* __restrict__ edge, const float* __restrict__ u,
    const int* __restrict__ batch)
{
    extern __shared__ char smem[];
    const uint32_t sbase = smem_to_u32(smem);
    const int tid   = threadIdx.x;
    const int wid   = tid >> 5;
    const int lane  = tid & 31;
    const int g     = lane >> 2;       // 0..7
    const int t     = lane & 3;        // 0..3
    const int warp_m = wid & 1;        // 2 row-warps of 64 rows
    const int warp_n = wid >> 1;       // 4 col-warps of 64 cols
    const int m0 = blockIdx.x * TILE_M;
    const int NK = (LAYER == 0) ? (K1 / BK) : (K2 / BK);

    float* aff = (float*)(smem + SM_AFF);
    if (LAYER == 1) {
        aff[tid]       = g_scale1[tid];
        aff[256 + tid] = g_shift1[tid];
        __syncthreads();
    }

    float acc[4][8][4];
    #pragma unroll
    for (int mt = 0; mt < 4; mt++)
        #pragma unroll
        for (int nt = 0; nt < 8; nt++)
            #pragma unroll
            for (int j = 0; j < 4; j++) acc[mt][nt][j] = 0.f;

    load_tiles<LAYER>(smem, sbase, 0, 0, tid, m0, src, dst, edge, u, batch);

    for (int kc = 0; kc < NK; kc++) {
        const int buf = kc & 1;
        if (kc + 1 < NK) {
            load_tiles<LAYER>(smem, sbase, buf ^ 1, kc + 1, tid, m0, src, dst, edge, u, batch);
            asm volatile("cp.async.wait_group 1;" ::: "memory");
        } else {
            asm volatile("cp.async.wait_group 0;" ::: "memory");
        }
        __syncthreads();

        const float* As  = (const float*)(smem + (buf ? SM_A1 : SM_A0));
        const char*  BsH = smem + (buf ? SM_B1 : SM_B0);
        const float* Ap  = As + (warp_m * 64 + g) * ASTR + 2 * t;
        // b fragment base: n-row (warp_n*64 + g), k byte offset t*4
        const char*  Bp  = BsH + (uint32_t)(warp_n * 64 + g) * (BSTRH * 2) + t * 4;

        #pragma unroll
        for (int ks = 0; ks < 2; ks++) {          // two k16 steps per BK=32
            // ---- A fragments (f32 pairs -> packed half2) ----
            uint32_t ua[4][4];
            #pragma unroll
            for (int mt = 0; mt < 4; mt++) {
                float2 p0 = *(const float2*)(Ap + (mt * 16    ) * ASTR + ks * 16    );
                float2 p1 = *(const float2*)(Ap + (mt * 16 + 8) * ASTR + ks * 16    );
                float2 p2 = *(const float2*)(Ap + (mt * 16    ) * ASTR + ks * 16 + 8);
                float2 p3 = *(const float2*)(Ap + (mt * 16 + 8) * ASTR + ks * 16 + 8);
                if (LAYER == 1) {
                    const int kk = kc * 32 + ks * 16 + 2 * t;
                    float2 sc  = *(const float2*)(aff + kk);
                    float2 sh  = *(const float2*)(aff + 256 + kk);
                    float2 sc8 = *(const float2*)(aff + kk + 8);
                    float2 sh8 = *(const float2*)(aff + 256 + kk + 8);
                    p0.x = fmaxf(fmaf(p0.x, sc.x,  sh.x ), 0.f);
                    p0.y = fmaxf(fmaf(p0.y, sc.y,  sh.y ), 0.f);
                    p1.x = fmaxf(fmaf(p1.x, sc.x,  sh.x ), 0.f);
                    p1.y = fmaxf(fmaf(p1.y, sc.y,  sh.y ), 0.f);
                    p2.x = fmaxf(fmaf(p2.x, sc8.x, sh8.x), 0.f);
                    p2.y = fmaxf(fmaf(p2.y, sc8.y, sh8.y), 0.f);
                    p3.x = fmaxf(fmaf(p3.x, sc8.x, sh8.x), 0.f);
                    p3.y = fmaxf(fmaf(p3.y, sc8.y, sh8.y), 0.f);
                }
                ua[mt][0] = pack_h2(p0.x, p0.y);
                ua[mt][1] = pack_h2(p1.x, p1.y);
                ua[mt][2] = pack_h2(p2.x, p2.y);
                ua[mt][3] = pack_h2(p3.x, p3.y);
            }

            // ---- B fragments: b0 = k{2t,2t+1}, b1 = k{2t+8,2t+9} at col n ----
            uint32_t b0[8], b1[8];
            #pragma unroll
            for (int nt = 0; nt < 8; nt++) {
                const char* bp = Bp + nt * 8 * (BSTRH * 2) + ks * 32;
                b0[nt] = *(const uint32_t*)(bp);
                b1[nt] = *(const uint32_t*)(bp + 16);
            }

            #pragma unroll
            for (int mt = 0; mt < 4; mt++)
                #pragma unroll
                for (int nt = 0; nt < 8; nt++)
                    mma16(acc[mt][nt], ua[mt], b0[nt], b1[nt]);
        }
        __syncthreads();
    }

    // ================= Epilogue: store y + column sum/sumsq partials ========
    float* __restrict__ ybuf = (LAYER == 0) ? g_y1 : g_y2;
    float* sm_ps = (float*)(smem + SM_A0);          // [2][256]
    float* sm_sq = sm_ps + 2 * OUT_N;               // [2][256]

    const int r_base = m0 + warp_m * 64 + g;

    #pragma unroll
    for (int nt = 0; nt < 8; nt++) {
        const int col = warp_n * 64 + nt * 8 + 2 * t;
        float v0 = 0.f, v1 = 0.f, q0 = 0.f, q1 = 0.f;
        #pragma unroll
        for (int mt = 0; mt < 4; mt++) {
            const long long r1 = r_base + mt * 16;
            const long long r2 = r1 + 8;
            float c0 = acc[mt][nt][0], c1 = acc[mt][nt][1];
            float c2 = acc[mt][nt][2], c3 = acc[mt][nt][3];
            if (r1 < E_ROWS) {
                *(float2*)(ybuf + r1 * OUT_N + col) = make_float2(c0, c1);
                v0 += c0; v1 += c1; q0 += c0 * c0; q1 += c1 * c1;
            }
            if (r2 < E_ROWS) {
                *(float2*)(ybuf + r2 * OUT_N + col) = make_float2(c2, c3);
                v0 += c2; v1 += c3; q0 += c2 * c2; q1 += c3 * c3;
            }
        }
        // reduce over the 8 lanes sharing t (g spans lane bits 2..4)
        #pragma unroll
        for (int o = 4; o < 32; o <<= 1) {
            v0 += __shfl_xor_sync(0xffffffffu, v0, o);
            v1 += __shfl_xor_sync(0xffffffffu, v1, o);
            q0 += __shfl_xor_sync(0xffffffffu, q0, o);
            q1 += __shfl_xor_sync(0xffffffffu, q1, o);
        }
        if (g == 0) {
            sm_ps[warp_m * OUT_N + col]     = v0;
            sm_ps[warp_m * OUT_N + col + 1] = v1;
            sm_sq[warp_m * OUT_N + col]     = q0;
            sm_sq[warp_m * OUT_N + col + 1] = q1;
        }
    }
    __syncthreads();

    {
        float s = sm_ps[tid] + sm_ps[OUT_N + tid];
        float q = sm_sq[tid] + sm_sq[OUT_N + tid];
        g_part_sum[(size_t)blockIdx.x * OUT_N + tid] = s;
        g_part_sq [(size_t)blockIdx.x * OUT_N + tid] = q;
    }
}

// ============================================================================
// Kernel 3/5: finalize BN stats — parallel deterministic reduction.
// ============================================================================
__global__ __launch_bounds__(256) void k_reduce(
    const float* __restrict__ g, const float* __restrict__ b, int layer)
{
    const int c   = blockIdx.x;    // column 0..255
    const int tid = threadIdx.x;   // 0..255

    double s = 0.0, q = 0.0;
    for (int t = tid; t < N_TILES; t += 256) {
        s += (double)g_part_sum[(size_t)t * OUT_N + c];
        q += (double)g_part_sq [(size_t)t * OUT_N + c];
    }

    __shared__ double ss[256];
    __shared__ double sq[256];
    ss[tid] = s; sq[tid] = q;
    __syncthreads();
    #pragma unroll
    for (int o = 128; o > 0; o >>= 1) {
        if (tid < o) { ss[tid] += ss[tid + o]; sq[tid] += sq[tid + o]; }
        __syncthreads();
    }

    if (tid == 0) {
        double m   = ss[0] / (double)E_ROWS;
        double var = sq[0] / (double)E_ROWS - m * m;
        float rstd = (float)(1.0 / sqrt(var + BN_EPS));
        float scale = g[c] * rstd;
        float shift = b[c] - (float)m * scale;
        if (layer == 0) { g_scale1[c] = scale; g_shift1[c] = shift; }
        else            { g_scale2[c] = scale; g_shift2[c] = shift; }
    }
}

// ============================================================================
// Kernel 6: out = y2 * scale2 + shift2
// ============================================================================
__global__ void k_finalize(float* __restrict__ out) {
    size_t i = (size_t)blockIdx.x * blockDim.x + threadIdx.x;   // float4 index
    if (i >= (size_t)E_ROWS * (OUT_N / 4)) return;
    int c = (int)((i & (OUT_N / 4 - 1)) * 4);
    float4 v  = ((const float4*)g_y2)[i];
    float4 sc = *(const float4*)(g_scale2 + c);
    float4 sh = *(const float4*)(g_shift2 + c);
    v.x = fmaf(v.x, sc.x, sh.x);
    v.y = fmaf(v.y, sc.y, sh.y);
    v.z = fmaf(v.z, sc.z, sh.z);
    v.w = fmaf(v.w, sc.w, sh.w);
    ((float4*)out)[i] = v;
}

// ============================================================================
// kernel_launch
// ============================================================================
extern "C" void kernel_launch(void* const* d_in, const int* in_sizes, int n_in,
                              void* d_out, int out_size) {
    (void)in_sizes; (void)n_in; (void)out_size;
    const float* src   = (const float*)d_in[0];
    const float* dst   = (const float*)d_in[1];
    const float* edge  = (const float*)d_in[2];
    const float* u     = (const float*)d_in[3];
    const int*   batch = (const int*)d_in[4];     // int32 (JAX x64 disabled)
    const float* W1    = (const float*)d_in[5];
    const float* g1    = (const float*)d_in[6];
    const float* b1    = (const float*)d_in[7];
    const float* W2    = (const float*)d_in[8];
    const float* g2    = (const float*)d_in[9];
    const float* b2    = (const float*)d_in[10];
    float* out = (float*)d_out;

    cudaFuncSetAttribute(k_gemm<0>, cudaFuncAttributeMaxDynamicSharedMemorySize, SMEM_TOTAL);
    cudaFuncSetAttribute(k_gemm<1>, cudaFuncAttributeMaxDynamicSharedMemorySize, SMEM_TOTAL);

    k_prep<<<(K1 * OUT_N + K2 * OUT_N + 255) / 256, 256>>>(W1, W2);
    k_gemm<0><<<N_TILES, THREADS, SMEM_TOTAL>>>(src, dst, edge, u, batch);
    k_reduce<<<OUT_N, 256>>>(g1, b1, 0);
    k_gemm<1><<<N_TILES, THREADS, SMEM_TOTAL>>>(src, dst, edge, u, batch);
    k_reduce<<<OUT_N, 256>>>(g2, b2, 1);
    k_finalize<<<(int)(((size_t)E_ROWS * (OUT_N / 4) + 255) / 256), 256>>>(out);
}